// round 6
// baseline (speedup 1.0000x reference)
#include <cuda_runtime.h>

// RollingBufferCache: B=4, H=8, S=512, D=128, BUF=4096.
// Output = [k_window ; v_window], each [B,H,W,D] with W = min(cur, BUF).
// W == BUF here, so every physical slot appears exactly once in the window:
// scatter+gather collapses to a per-row source selection:
//   w >= W-S  -> new chunk row (w - (W-S))
//   otherwise -> cache row (cur - W + w) & (BUF-1)
//
// R5: persistent single-wave grid (148 SMs x 6 CTAs = 888 CTAs) looping over
// the 8192 32-row tiles. Eliminates ~9 wave transitions and per-CTA prologue
// re-execution of the 8192-CTA launch. Loop body is the proven R2 structure:
// 4 front-batched .cs float4 loads -> 4 .cs stores (MLP=4/warp, 26-32 regs).

#define ROLL_D4   32    // D/4 float4 per row (D=128)
#define ROLL_BH   32    // B*H
#define ROLL_BUF  4096
#define ROLL_S    512
#define GRID_CTAS 888   // 148 SMs * 6 resident CTAs @ 256 thr / ~32 regs

__global__ void __launch_bounds__(256)
RollingBufferCache_kernel(const float4* __restrict__ k,
                          const float4* __restrict__ v,
                          const float4* __restrict__ kc,
                          const float4* __restrict__ vc,
                          const int*    __restrict__ cur_p,
                          float4*       __restrict__ out,
                          int W)
{
    const int cur  = __ldg(cur_p);        // device scalar (graph-capturable)
    const int lane = threadIdx.x & 31;
    const int warp = threadIdx.x >> 5;

    const int ntpb    = W >> 5;           // 32-row tiles per (sel,bh)
    const int per_sel = ROLL_BH * ntpb;   // tiles per k/v half
    const int ntiles  = 2 * per_sel;

    const int off    = cur - W;           // logical start of window
    const int wsplit = W - ROLL_S;        // rows >= wsplit come from new chunk

    for (int t = blockIdx.x; t < ntiles; t += GRID_CTAS) {
        const int sel  = t / per_sel;
        const int rem  = t - sel * per_sel;
        const int bh   = rem / ntpb;
        const int tile = rem - bh * ntpb;

        const float4* src_new = sel ? v  : k;
        const float4* src_old = sel ? vc : kc;
        float4* out_base = out +
            ((size_t)(sel * ROLL_BH + bh) * (size_t)W) * ROLL_D4;

        // Tile = 32 consecutive rows; 8 warps x 4 rows, one float4 per lane.
        // W is a multiple of 32 -> no bounds checks.
        const int w0 = tile * 32 + warp;

        const float4* srow[4];
        #pragma unroll
        for (int r = 0; r < 4; ++r) {
            const int w = w0 + r * 8;
            if (w >= wsplit) {
                srow[r] = src_new +
                    ((size_t)bh * ROLL_S + (size_t)(w - wsplit)) * ROLL_D4;
            } else {
                const int phys = (off + w) & (ROLL_BUF - 1);
                srow[r] = src_old +
                    ((size_t)bh * ROLL_BUF + (size_t)phys) * ROLL_D4;
            }
        }

        float4 val[4];
        #pragma unroll
        for (int r = 0; r < 4; ++r)
            val[r] = __ldcs(srow[r] + lane);   // evict-first single-use stream

        #pragma unroll
        for (int r = 0; r < 4; ++r)
            __stcs(out_base + (size_t)(w0 + r * 8) * ROLL_D4 + lane, val[r]);
    }
}

extern "C" void kernel_launch(void* const* d_in, const int* in_sizes, int n_in,
                              void* d_out, int out_size)
{
    const float4* k  = (const float4*)d_in[0];
    const float4* v  = (const float4*)d_in[1];
    const float4* kc = (const float4*)d_in[2];
    const float4* vc = (const float4*)d_in[3];
    const int*   cur = (const int*)d_in[4];

    // out_size = 2 * BH * W * D  ->  W
    const int W = out_size / (2 * ROLL_BH * 128);

    RollingBufferCache_kernel<<<GRID_CTAS, 256>>>(k, v, kc, vc, cur,
                                                  (float4*)d_out, W);
}

// round 7
// speedup vs baseline: 1.0808x; 1.0808x over previous
#include <cuda_runtime.h>

// RollingBufferCache: B=4, H=8, S=512, D=128, BUF=4096.
// Output = [k_window ; v_window], each [B,H,W,D] with W = min(cur, BUF).
// W == BUF here, so every physical slot appears exactly once in the window:
// scatter+gather collapses to a per-row source selection:
//   w >= W-S  -> new chunk row (w - (W-S))
//   otherwise -> cache row (cur - W + w) & (BUF-1)
//
// R6: R2 structure (best kernel time: 4 front-batched .cs float4 loads ->
// 4 .cs stores per warp, 32-row tiles) but each CTA handles 4 consecutive
// tiles via a fully-unrolled loop with add-only indexing (sel/bh stay in
// blockIdx.z/y — R5 showed in-loop div/mod indexing costs 15% issue and
// occupancy). Grid 8192 -> 2048 CTAs (~2.3 waves): amortizes per-CTA
// prologue and wave transitions without R5's ALU tax.

#define ROLL_D4   32    // D/4 float4 per row (D=128)
#define ROLL_BH   32    // B*H
#define ROLL_BUF  4096
#define ROLL_S    512
#define TILES_PER_CTA 4 // 4 x 32 = 128 rows per CTA

__global__ void __launch_bounds__(256)
RollingBufferCache_kernel(const float4* __restrict__ k,
                          const float4* __restrict__ v,
                          const float4* __restrict__ kc,
                          const float4* __restrict__ vc,
                          const int*    __restrict__ cur_p,
                          float4*       __restrict__ out,
                          int W)
{
    const int cur  = __ldg(cur_p);        // device scalar (graph-capturable)
    const int sel  = blockIdx.z;          // 0 = k path, 1 = v path
    const int bh   = blockIdx.y;          // flattened (b,h)
    const int lane = threadIdx.x & 31;
    const int warp = threadIdx.x >> 5;

    const float4* src_new = sel ? v  : k;
    const float4* src_old = sel ? vc : kc;
    float4* out_base = out + ((size_t)(sel * ROLL_BH + bh) * (size_t)W) * ROLL_D4;

    const int off    = cur - W;           // logical start of window
    const int wsplit = W - ROLL_S;        // rows >= wsplit come from new chunk

    // CTA covers TILES_PER_CTA consecutive 32-row tiles; per tile each of the
    // 8 warps handles 4 rows (stride 8), one float4 per lane. W is a multiple
    // of 128 for this grid -> no bounds checks. Indexing is add-only.
    const int wcta = blockIdx.x * (32 * TILES_PER_CTA) + warp;

    #pragma unroll
    for (int it = 0; it < TILES_PER_CTA; ++it) {
        const int w0 = wcta + it * 32;

        // Front-batch the 4 independent loads (MLP=4 per thread).
        const float4* srow[4];
        #pragma unroll
        for (int r = 0; r < 4; ++r) {
            const int w = w0 + r * 8;
            if (w >= wsplit) {
                srow[r] = src_new +
                    ((size_t)bh * ROLL_S + (size_t)(w - wsplit)) * ROLL_D4;
            } else {
                const int phys = (off + w) & (ROLL_BUF - 1);
                srow[r] = src_old +
                    ((size_t)bh * ROLL_BUF + (size_t)phys) * ROLL_D4;
            }
        }

        float4 val[4];
        #pragma unroll
        for (int r = 0; r < 4; ++r)
            val[r] = __ldcs(srow[r] + lane);   // evict-first single-use stream

        #pragma unroll
        for (int r = 0; r < 4; ++r)
            __stcs(out_base + (size_t)(w0 + r * 8) * ROLL_D4 + lane, val[r]);
    }
}

extern "C" void kernel_launch(void* const* d_in, const int* in_sizes, int n_in,
                              void* d_out, int out_size)
{
    const float4* k  = (const float4*)d_in[0];
    const float4* v  = (const float4*)d_in[1];
    const float4* kc = (const float4*)d_in[2];
    const float4* vc = (const float4*)d_in[3];
    const int*   cur = (const int*)d_in[4];

    // out_size = 2 * BH * W * D  ->  W
    const int W = out_size / (2 * ROLL_BH * 128);

    dim3 grid(W / (32 * TILES_PER_CTA), ROLL_BH, 2);
    RollingBufferCache_kernel<<<grid, 256>>>(k, v, kc, vc, cur,
                                             (float4*)d_out, W);
}

// round 8
// speedup vs baseline: 1.0931x; 1.0114x over previous
#include <cuda_runtime.h>

// RollingBufferCache: B=4, H=8, S=512, D=128, BUF=4096.
// Output = [k_window ; v_window], each [B,H,W,D] with W = min(cur, BUF).
// W == BUF here, so every physical slot appears exactly once in the window:
// scatter+gather collapses to a per-row source selection:
//   w >= W-S  -> new chunk row (w - (W-S))
//   otherwise -> cache row (cur - W + w) & (BUF-1)
//
// R7 (final): the R2 structure — measured fastest kernel across 6 variants
// (36.5us = 268MB at 7.34 TB/s combined R+W, ~92% of HBM3e spec, i.e. the
// memory floor for a fully mixed read/write stream). One warp per 512B row,
// 4 rows per warp with front-batched loads (MLP=4/thread), streaming
// evict-first policy both directions, 32 regs -> 82% occupancy. Wider
// accesses (v8), persistent grids, CTA reuse, and phase barriers were all
// measured neutral-to-negative (occupancy/ALU costs exceed any gain).

#define ROLL_D4   32    // D/4 float4 per row (D=128)
#define ROLL_BH   32    // B*H
#define ROLL_BUF  4096
#define ROLL_S    512

__global__ void __launch_bounds__(256)
RollingBufferCache_kernel(const float4* __restrict__ k,
                          const float4* __restrict__ v,
                          const float4* __restrict__ kc,
                          const float4* __restrict__ vc,
                          const int*    __restrict__ cur_p,
                          float4*       __restrict__ out,
                          int W)
{
    const int cur  = __ldg(cur_p);        // device scalar (graph-capturable)
    const int sel  = blockIdx.z;          // 0 = k path, 1 = v path
    const int bh   = blockIdx.y;          // flattened (b,h)
    const int lane = threadIdx.x & 31;
    const int warp = threadIdx.x >> 5;

    const float4* src_new = sel ? v  : k;
    const float4* src_old = sel ? vc : kc;
    float4* out_base = out + ((size_t)(sel * ROLL_BH + bh) * (size_t)W) * ROLL_D4;

    const int off    = cur - W;           // logical start of window
    const int wsplit = W - ROLL_S;        // rows >= wsplit come from new chunk

    // Each block covers 32 consecutive rows of one (sel,bh); 8 warps,
    // each warp does 4 rows (512 B each), one float4 per lane.
    // W is a multiple of 32 for this grid -> no bounds checks.
    const int w0 = blockIdx.x * 32 + warp;

    // Phase 1: compute all 4 source addresses, issue all 4 loads (MLP=4).
    const float4* srow[4];
    #pragma unroll
    for (int r = 0; r < 4; ++r) {
        const int w = w0 + r * 8;
        if (w >= wsplit) {
            srow[r] = src_new + ((size_t)bh * ROLL_S + (size_t)(w - wsplit)) * ROLL_D4;
        } else {
            const int phys = (off + w) & (ROLL_BUF - 1);
            srow[r] = src_old + ((size_t)bh * ROLL_BUF + (size_t)phys) * ROLL_D4;
        }
    }

    float4 val[4];
    #pragma unroll
    for (int r = 0; r < 4; ++r)
        val[r] = __ldcs(srow[r] + lane);   // evict-first: single-use stream

    // Phase 2: store all 4 (streaming, evict-first).
    #pragma unroll
    for (int r = 0; r < 4; ++r)
        __stcs(out_base + (size_t)(w0 + r * 8) * ROLL_D4 + lane, val[r]);
}

extern "C" void kernel_launch(void* const* d_in, const int* in_sizes, int n_in,
                              void* d_out, int out_size)
{
    const float4* k  = (const float4*)d_in[0];
    const float4* v  = (const float4*)d_in[1];
    const float4* kc = (const float4*)d_in[2];
    const float4* vc = (const float4*)d_in[3];
    const int*   cur = (const int*)d_in[4];

    // out_size = 2 * BH * W * D  ->  W
    const int W = out_size / (2 * ROLL_BH * 128);

    dim3 grid((W + 31) / 32, ROLL_BH, 2);
    RollingBufferCache_kernel<<<grid, 256>>>(k, v, kc, vc, cur,
                                             (float4*)d_out, W);
}